// round 2
// baseline (speedup 1.0000x reference)
#include <cuda_runtime.h>
#include <cuda_bf16.h>

#define N_TOK 16384
#define DDIM  1024
#define NEXP  8

#define BM 128
#define BN 128
#define BK 16

// Scratch (no allocations allowed): per-expert token counts + gathered indices.
__device__ int g_cnt[NEXP];
__device__ int g_idx[NEXP * N_TOK];

// ---------------------------------------------------------------------------
// Kernel 0: zero the per-expert counters (must run every launch; graph replay).
// ---------------------------------------------------------------------------
__global__ void zero_cnt_kernel() {
    if (threadIdx.x < NEXP) g_cnt[threadIdx.x] = 0;
}

// ---------------------------------------------------------------------------
// Kernel 1: router. One warp per token. logits = x @ rw.T + rb ; argmax with
// first-index tie-break (strict >), then atomic append into expert bucket.
// ---------------------------------------------------------------------------
__global__ void router_kernel(const float* __restrict__ x,
                              const float* __restrict__ rw,
                              const float* __restrict__ rb) {
    int gwarp = (int)((blockIdx.x * blockDim.x + threadIdx.x) >> 5);
    int lane  = threadIdx.x & 31;
    if (gwarp >= N_TOK) return;

    const float* xr = x + (size_t)gwarp * DDIM;
    float acc[NEXP];
#pragma unroll
    for (int e = 0; e < NEXP; e++) acc[e] = 0.f;

    for (int k = lane; k < DDIM; k += 32) {
        float xv = __ldg(xr + k);
#pragma unroll
        for (int e = 0; e < NEXP; e++)
            acc[e] = fmaf(xv, __ldg(rw + e * DDIM + k), acc[e]);
    }
#pragma unroll
    for (int e = 0; e < NEXP; e++) {
#pragma unroll
        for (int off = 16; off; off >>= 1)
            acc[e] += __shfl_xor_sync(0xffffffffu, acc[e], off);
    }
    if (lane == 0) {
        int   best = 0;
        float bv   = acc[0] + rb[0];
#pragma unroll
        for (int e = 1; e < NEXP; e++) {
            float v = acc[e] + rb[e];
            if (v > bv) { bv = v; best = e; }   // strict > : first max wins
        }
        int pos = atomicAdd(&g_cnt[best], 1);
        g_idx[best * N_TOK + pos] = gwarp;
    }
}

// ---------------------------------------------------------------------------
// Kernel 2: grouped gather-GEMM (double-buffered smem).
//   out[tok, n] = sum_k x[tok, k] * ew[e, n, k] + eb[e, n]
// Tile: BM=128 gathered tokens x BN=128 outputs x BK=16, 256 threads,
// 8x8 register tile per thread, register prefetch + smem ping-pong
// (ONE __syncthreads per k-tile).
// Grid is data-independent: (D/BN, N/BM, E); blocks past the expert's token
// count exit immediately.
// ---------------------------------------------------------------------------
__global__ __launch_bounds__(256, 2)
void moe_gemm_kernel(const float* __restrict__ x,
                     const float* __restrict__ ew,
                     const float* __restrict__ eb,
                     float* __restrict__ out) {
    const int e   = blockIdx.z;
    const int cnt = g_cnt[e];
    const int m0  = blockIdx.y * BM;
    if (m0 >= cnt) return;
    const int n0  = blockIdx.x * BN;

    __shared__ __align__(16) float As[2][BK][BM];   // [buf][k][token-in-tile]
    __shared__ __align__(16) float Bs[2][BK][BN];   // [buf][k][out-in-tile]
    __shared__ int srow[BM];

    const int tid = threadIdx.x;
    const int tx  = tid & 15;    // output group (8 cols)
    const int ty  = tid >> 4;    // token group  (8 rows)

    // Gather token indices for this tile (clamp padding rows to a valid token;
    // their results are discarded at store time).
    if (tid < BM) {
        int r = m0 + tid;
        srow[tid] = g_idx[e * N_TOK + (r < cnt ? r : m0)];
    }
    __syncthreads();

    // Each thread loads 2 float4 of A and 2 float4 of B per k-tile.
    // Linear id in [0,512): row = id>>2 (0..127), kq = id&3 (which float4).
    const int idA0  = tid;
    const int idA1  = tid + 256;
    const int rowL0 = idA0 >> 2, kq0 = idA0 & 3;
    const int rowL1 = idA1 >> 2, kq1 = idA1 & 3;

    const float* gB = ew + (size_t)e * DDIM * DDIM + (size_t)n0 * DDIM;
    const int tok0 = srow[rowL0];
    const int tok1 = srow[rowL1];
    const float* gA0 = x + (size_t)tok0 * DDIM + kq0 * 4;
    const float* gA1 = x + (size_t)tok1 * DDIM + kq1 * 4;
    const float* gB0 = gB + (size_t)rowL0 * DDIM + kq0 * 4;
    const float* gB1 = gB + (size_t)rowL1 * DDIM + kq1 * 4;

    float4 pa0 = *(const float4*)(gA0);
    float4 pa1 = *(const float4*)(gA1);
    float4 pb0 = *(const float4*)(gB0);
    float4 pb1 = *(const float4*)(gB1);

    float accum[8][8];
#pragma unroll
    for (int i = 0; i < 8; i++)
#pragma unroll
        for (int j = 0; j < 8; j++) accum[i][j] = 0.f;

    // Commit tile 0 into buffer 0.
    As[0][kq0 * 4 + 0][rowL0] = pa0.x;
    As[0][kq0 * 4 + 1][rowL0] = pa0.y;
    As[0][kq0 * 4 + 2][rowL0] = pa0.z;
    As[0][kq0 * 4 + 3][rowL0] = pa0.w;
    As[0][kq1 * 4 + 0][rowL1] = pa1.x;
    As[0][kq1 * 4 + 1][rowL1] = pa1.y;
    As[0][kq1 * 4 + 2][rowL1] = pa1.z;
    As[0][kq1 * 4 + 3][rowL1] = pa1.w;
    Bs[0][kq0 * 4 + 0][rowL0] = pb0.x;
    Bs[0][kq0 * 4 + 1][rowL0] = pb0.y;
    Bs[0][kq0 * 4 + 2][rowL0] = pb0.z;
    Bs[0][kq0 * 4 + 3][rowL0] = pb0.w;
    Bs[0][kq1 * 4 + 0][rowL1] = pb1.x;
    Bs[0][kq1 * 4 + 1][rowL1] = pb1.y;
    Bs[0][kq1 * 4 + 2][rowL1] = pb1.z;
    Bs[0][kq1 * 4 + 3][rowL1] = pb1.w;
    __syncthreads();

    const int NT = DDIM / BK;   // 64 k-tiles
    int buf = 0;
    for (int t = 0; t < NT; t++) {
        // Prefetch next tile to registers (overlaps with FMA below).
        if (t + 1 < NT) {
            const int koff = (t + 1) * BK;
            pa0 = *(const float4*)(gA0 + koff);
            pa1 = *(const float4*)(gA1 + koff);
            pb0 = *(const float4*)(gB0 + koff);
            pb1 = *(const float4*)(gB1 + koff);
        }

#pragma unroll
        for (int k = 0; k < BK; k++) {
            float a[8], b[8];
            *(float4*)&a[0] = *(const float4*)&As[buf][k][ty * 8];
            *(float4*)&a[4] = *(const float4*)&As[buf][k][ty * 8 + 4];
            *(float4*)&b[0] = *(const float4*)&Bs[buf][k][tx * 8];
            *(float4*)&b[4] = *(const float4*)&Bs[buf][k][tx * 8 + 4];
#pragma unroll
            for (int i = 0; i < 8; i++)
#pragma unroll
                for (int j = 0; j < 8; j++)
                    accum[i][j] = fmaf(a[i], b[j], accum[i][j]);
        }

        // Commit prefetched tile into the other buffer; single barrier/iter.
        // Writes touch buf^1 only, so they cannot race the reads of buf above.
        if (t + 1 < NT) {
            const int nb = buf ^ 1;
            As[nb][kq0 * 4 + 0][rowL0] = pa0.x;
            As[nb][kq0 * 4 + 1][rowL0] = pa0.y;
            As[nb][kq0 * 4 + 2][rowL0] = pa0.z;
            As[nb][kq0 * 4 + 3][rowL0] = pa0.w;
            As[nb][kq1 * 4 + 0][rowL1] = pa1.x;
            As[nb][kq1 * 4 + 1][rowL1] = pa1.y;
            As[nb][kq1 * 4 + 2][rowL1] = pa1.z;
            As[nb][kq1 * 4 + 3][rowL1] = pa1.w;
            Bs[nb][kq0 * 4 + 0][rowL0] = pb0.x;
            Bs[nb][kq0 * 4 + 1][rowL0] = pb0.y;
            Bs[nb][kq0 * 4 + 2][rowL0] = pb0.z;
            Bs[nb][kq0 * 4 + 3][rowL0] = pb0.w;
            Bs[nb][kq1 * 4 + 0][rowL1] = pb1.x;
            Bs[nb][kq1 * 4 + 1][rowL1] = pb1.y;
            Bs[nb][kq1 * 4 + 2][rowL1] = pb1.z;
            Bs[nb][kq1 * 4 + 3][rowL1] = pb1.w;
            __syncthreads();
            buf = nb;
        }
    }

    // Epilogue: add bias, scatter-store to out[token].
    float bias[8];
    *(float4*)&bias[0] = *(const float4*)(eb + (size_t)e * DDIM + n0 + tx * 8);
    *(float4*)&bias[4] = *(const float4*)(eb + (size_t)e * DDIM + n0 + tx * 8 + 4);

#pragma unroll
    for (int i = 0; i < 8; i++) {
        int r = ty * 8 + i;
        if (m0 + r < cnt) {
            int tok = srow[r];
            float* o = out + (size_t)tok * DDIM + n0 + tx * 8;
            float4 v0, v1;
            v0.x = accum[i][0] + bias[0];
            v0.y = accum[i][1] + bias[1];
            v0.z = accum[i][2] + bias[2];
            v0.w = accum[i][3] + bias[3];
            v1.x = accum[i][4] + bias[4];
            v1.y = accum[i][5] + bias[5];
            v1.z = accum[i][6] + bias[6];
            v1.w = accum[i][7] + bias[7];
            *(float4*)(o)     = v0;
            *(float4*)(o + 4) = v1;
        }
    }
}

// ---------------------------------------------------------------------------
// kernel_launch
// inputs (metadata order): x[N,D] f32, router_w[E,D] f32, router_b[E] f32,
//                          expert_w[E,D,D] f32, expert_b[E,D] f32
// output: f32 [N, D]
// ---------------------------------------------------------------------------
extern "C" void kernel_launch(void* const* d_in, const int* in_sizes, int n_in,
                              void* d_out, int out_size) {
    const float* x  = (const float*)d_in[0];
    const float* rw = (const float*)d_in[1];
    const float* rb = (const float*)d_in[2];
    const float* ew = (const float*)d_in[3];
    const float* eb = (const float*)d_in[4];
    float* out = (float*)d_out;

    zero_cnt_kernel<<<1, 32>>>();
    router_kernel<<<N_TOK / 8, 256>>>(x, rw, rb);

    dim3 grid(DDIM / BN, N_TOK / BM, NEXP);
    moe_gemm_kernel<<<grid, 256>>>(x, ew, eb, out);
}

// round 10
// speedup vs baseline: 1.9804x; 1.9804x over previous
#include <cuda_runtime.h>
#include <cuda_bf16.h>
#include <cstdint>

#define N_TOK 16384
#define DDIM  1024
#define NEXP  8

#define BM 128
#define BN 128
#define BK 64
#define NCHUNK (DDIM / BK)       // 16
#define GT 256                   // 8 warps

// ---- shared memory layout ----
// f32 staging (double buffered): rows padded to 68 floats (272 B, 16B-aligned)
#define FSTR   68
#define FROWB  (FSTR * 4)                 // 272 B
#define FMATB  (BM * FROWB)               // 34816 B per f32 tile
#define FSTAGEB (2 * FMATB)               // A + B = 69632 B per stage
// bf16 tiles (single buffer, rebuilt every chunk): rows padded to 72 bf16 (144 B)
#define ROWB   144
#define MATB   (BM * ROWB)                // 18432 B
#define OFF_AHI 0
#define OFF_ALO (1 * MATB)
#define OFF_BHI (2 * MATB)
#define OFF_BLO (3 * MATB)
#define SM_SROW 0
#define SM_F32  512
#define SM_BF   (SM_F32 + 2 * FSTAGEB)    // 139776
#define SMEM_TOTAL (SM_BF + 4 * MATB)     // 213504 B  (< 227 KB)

// ---------------------------------------------------------------------------
// Device scratch: ONLY the small routing tables (no large global arrays).
// ---------------------------------------------------------------------------
__device__ int g_cnt[NEXP];
__device__ int g_idx[NEXP * N_TOK];

// ---------------------------------------------------------------------------
// PTX helpers (sm_80-level only)
// ---------------------------------------------------------------------------
__device__ __forceinline__ uint32_t smem_u32(const void* p) {
    uint32_t a;
    asm("{ .reg .u64 t; cvta.to.shared.u64 t, %1; cvt.u32.u64 %0, t; }"
        : "=r"(a) : "l"(p));
    return a;
}
__device__ __forceinline__ void cp16(uint32_t dst, const void* src) {
    asm volatile("cp.async.cg.shared.global [%0], [%1], 16;"
                 :: "r"(dst), "l"(src) : "memory");
}
#define CP_COMMIT() asm volatile("cp.async.commit_group;" ::: "memory")
template <int N>
__device__ __forceinline__ void cp_wait() {
    asm volatile("cp.async.wait_group %0;" :: "n"(N) : "memory");
}
__device__ __forceinline__ void ldsm4(uint32_t& r0, uint32_t& r1,
                                      uint32_t& r2, uint32_t& r3, uint32_t a) {
    asm volatile("ldmatrix.sync.aligned.m8n8.x4.shared.b16 {%0,%1,%2,%3}, [%4];"
                 : "=r"(r0), "=r"(r1), "=r"(r2), "=r"(r3) : "r"(a));
}
__device__ __forceinline__ void mma16816(float* d, const uint32_t* a,
                                         const uint32_t* b) {
    asm volatile("mma.sync.aligned.m16n8k16.row.col.f32.bf16.bf16.f32 "
                 "{%0,%1,%2,%3}, {%4,%5,%6,%7}, {%8,%9}, {%0,%1,%2,%3};"
                 : "+f"(d[0]), "+f"(d[1]), "+f"(d[2]), "+f"(d[3])
                 : "r"(a[0]), "r"(a[1]), "r"(a[2]), "r"(a[3]),
                   "r"(b[0]), "r"(b[1]));
}
// Split a float pair into packed-bf16 hi and lo residual (lo = f - bf16(f)).
__device__ __forceinline__ void pack_split(float f0, float f1,
                                           uint32_t& hi, uint32_t& lo) {
    asm("cvt.rn.bf16x2.f32 %0, %1, %2;" : "=r"(hi) : "f"(f1), "f"(f0));
    float h0 = __uint_as_float(hi << 16);
    float h1 = __uint_as_float(hi & 0xffff0000u);
    float r0 = f0 - h0;
    float r1 = f1 - h1;
    asm("cvt.rn.bf16x2.f32 %0, %1, %2;" : "=r"(lo) : "f"(r1), "f"(r0));
}

// ---------------------------------------------------------------------------
// Kernel 0: zero per-expert counters.
// ---------------------------------------------------------------------------
__global__ void zero_cnt_kernel() {
    if (threadIdx.x < NEXP) g_cnt[threadIdx.x] = 0;
}

// ---------------------------------------------------------------------------
// Kernel 1: router. One warp/token; argmax, first-index tie-break.
// ---------------------------------------------------------------------------
__global__ void router_kernel(const float* __restrict__ x,
                              const float* __restrict__ rw,
                              const float* __restrict__ rb) {
    int gwarp = (int)((blockIdx.x * blockDim.x + threadIdx.x) >> 5);
    int lane  = threadIdx.x & 31;
    if (gwarp >= N_TOK) return;
    const float* xr = x + (size_t)gwarp * DDIM;
    float acc[NEXP];
#pragma unroll
    for (int e = 0; e < NEXP; e++) acc[e] = 0.f;
    for (int k = lane; k < DDIM; k += 32) {
        float xv = __ldg(xr + k);
#pragma unroll
        for (int e = 0; e < NEXP; e++)
            acc[e] = fmaf(xv, __ldg(rw + e * DDIM + k), acc[e]);
    }
#pragma unroll
    for (int e = 0; e < NEXP; e++)
#pragma unroll
        for (int off = 16; off; off >>= 1)
            acc[e] += __shfl_xor_sync(0xffffffffu, acc[e], off);
    if (lane == 0) {
        int best = 0;
        float bv = acc[0] + rb[0];
#pragma unroll
        for (int e = 1; e < NEXP; e++) {
            float v = acc[e] + rb[e];
            if (v > bv) { bv = v; best = e; }
        }
        int pos = atomicAdd(&g_cnt[best], 1);
        g_idx[best * N_TOK + pos] = gwarp;
    }
}

// ---------------------------------------------------------------------------
// Kernel 2: grouped gather-GEMM, mma.sync bf16 hi/lo split with IN-KERNEL
// f32->bf16 conversion (no global scratch, no separate convert kernels).
//   out[tok, n] = sum_k x[tok,k] * ew[e,n,k] + eb[e,n]
// Per chunk: cp.async f32 A/B tiles (double buffered) -> convert phase writes
// bf16 hi/lo tiles (ldmatrix layout) -> 4 k-steps x 48 HMMA.
// ---------------------------------------------------------------------------
__global__ __launch_bounds__(GT, 1)
void moe_gemm_mma(const float* __restrict__ x,
                  const float* __restrict__ ew,
                  const float* __restrict__ eb,
                  float* __restrict__ out) {
    const int e   = blockIdx.z;
    const int cnt = g_cnt[e];
    const int m0  = blockIdx.y * BM;
    if (m0 >= cnt) return;
    const int n0  = blockIdx.x * BN;

    extern __shared__ __align__(256) char smem[];
    int* srow = (int*)(smem + SM_SROW);
    const uint32_t sb = smem_u32(smem);
    const int tid  = threadIdx.x;
    const int lane = tid & 31;
    const int warp = tid >> 5;
    const int wm   = warp & 1;    // 0..1 -> 64-row half (M)
    const int wn   = warp >> 1;   // 0..3 -> 32-col quarter (N)

    if (tid < BM) {
        int r = m0 + tid;
        srow[tid] = g_idx[e * N_TOK + (r < cnt ? r : m0)];
    }
    __syncthreads();

    // ---- cp.async plan: 8 float4 of A + 8 of B per thread per chunk ----
    const float* wB = ew + ((size_t)e * DDIM + n0) * DDIM;
    size_t axoff[8], bxoff[8];
    uint32_t fdoff[8];
#pragma unroll
    for (int rep = 0; rep < 8; rep++) {
        int li    = tid + rep * GT;       // 0..2047
        int row   = li >> 4;              // 0..127
        int piece = li & 15;              // float4 index within 64-col row
        axoff[rep] = (size_t)srow[row] * DDIM + piece * 4;
        bxoff[rep] = (size_t)row * DDIM + piece * 4;
        fdoff[rep] = (uint32_t)(row * FROWB + piece * 16);
    }

    auto load_chunk = [&](int t, int s) {
        const size_t kg = (size_t)t * BK;
        const uint32_t st = sb + SM_F32 + (uint32_t)s * FSTAGEB;
#pragma unroll
        for (int rep = 0; rep < 8; rep++) {
            cp16(st + fdoff[rep],         x  + axoff[rep] + kg);
            cp16(st + fdoff[rep] + FMATB, wB + bxoff[rep] + kg);
        }
    };

    // ---- ldmatrix per-thread base offsets (within a bf16 tile) ----
    const uint32_t a_base =
        (uint32_t)((wm * 64 + (lane & 15)) * ROWB + ((lane >> 4) << 3) * 2);
    const uint32_t b_base =
        (uint32_t)((wn * 32 + (lane & 7) + ((lane >> 4) << 3)) * ROWB +
                   (((lane >> 3) & 1) << 3) * 2);

    float acc[4][4][4];
#pragma unroll
    for (int mi = 0; mi < 4; mi++)
#pragma unroll
        for (int nj = 0; nj < 4; nj++)
#pragma unroll
            for (int q = 0; q < 4; q++) acc[mi][nj][q] = 0.f;

    // Prologue: chunk 0 -> f32 stage 0.
    load_chunk(0, 0);
    CP_COMMIT();

    for (int t = 0; t < NCHUNK; t++) {
        const int s = t & 1;
        if (t + 1 < NCHUNK) {
            load_chunk(t + 1, s ^ 1);
            CP_COMMIT();
            cp_wait<1>();                 // chunk t resident, t+1 in flight
        } else {
            cp_wait<0>();
        }
        __syncthreads();                  // f32 stage s complete for all

        // ---- convert f32 stage s -> bf16 hi/lo tiles (ldmatrix layout) ----
        {
            const uint32_t fst = sb + SM_F32 + (uint32_t)s * FSTAGEB;
            const uint32_t bst = sb + SM_BF;
#pragma unroll
            for (int rep = 0; rep < 8; rep++) {
                int li    = tid + rep * GT;
                int row   = li >> 4;
                int piece = li & 15;
                uint32_t fsrc = fst + (uint32_t)(row * FROWB + piece * 16);
                uint32_t bdst = bst + (uint32_t)(row * ROWB + piece * 8);
                // A
                float4 va;
                asm volatile("ld.shared.v4.f32 {%0,%1,%2,%3}, [%4];"
                             : "=f"(va.x), "=f"(va.y), "=f"(va.z), "=f"(va.w)
                             : "r"(fsrc));
                uint32_t h0, l0, h1, l1;
                pack_split(va.x, va.y, h0, l0);
                pack_split(va.z, va.w, h1, l1);
                asm volatile("st.shared.v2.u32 [%0], {%1,%2};"
                             :: "r"(bdst + OFF_AHI), "r"(h0), "r"(h1));
                asm volatile("st.shared.v2.u32 [%0], {%1,%2};"
                             :: "r"(bdst + OFF_ALO), "r"(l0), "r"(l1));
                // B
                float4 vb;
                asm volatile("ld.shared.v4.f32 {%0,%1,%2,%3}, [%4];"
                             : "=f"(vb.x), "=f"(vb.y), "=f"(vb.z), "=f"(vb.w)
                             : "r"(fsrc + FMATB));
                pack_split(vb.x, vb.y, h0, l0);
                pack_split(vb.z, vb.w, h1, l1);
                asm volatile("st.shared.v2.u32 [%0], {%1,%2};"
                             :: "r"(bdst + OFF_BHI), "r"(h0), "r"(h1));
                asm volatile("st.shared.v2.u32 [%0], {%1,%2};"
                             :: "r"(bdst + OFF_BLO), "r"(l0), "r"(l1));
            }
        }
        __syncthreads();                  // bf16 tiles ready

        const uint32_t bst = sb + SM_BF;
        const uint32_t ahw = bst + OFF_AHI + a_base;
        const uint32_t alw = bst + OFF_ALO + a_base;
        const uint32_t bhw = bst + OFF_BHI + b_base;
        const uint32_t blw = bst + OFF_BLO + b_base;

#pragma unroll
        for (int ks = 0; ks < BK / 16; ks++) {           // 4 k-steps
            const uint32_t ko = (uint32_t)(ks * 16 * 2); // 32 B per k-step
            uint32_t ah[4][4], al[4][4], bh[4][2], bl[4][2];
#pragma unroll
            for (int mi = 0; mi < 4; mi++) {
                ldsm4(ah[mi][0], ah[mi][1], ah[mi][2], ah[mi][3],
                      ahw + (uint32_t)(mi * 16 * ROWB) + ko);
                ldsm4(al[mi][0], al[mi][1], al[mi][2], al[mi][3],
                      alw + (uint32_t)(mi * 16 * ROWB) + ko);
            }
#pragma unroll
            for (int nj2 = 0; nj2 < 2; nj2++) {
                ldsm4(bh[nj2 * 2][0], bh[nj2 * 2][1],
                      bh[nj2 * 2 + 1][0], bh[nj2 * 2 + 1][1],
                      bhw + (uint32_t)(nj2 * 16 * ROWB) + ko);
                ldsm4(bl[nj2 * 2][0], bl[nj2 * 2][1],
                      bl[nj2 * 2 + 1][0], bl[nj2 * 2 + 1][1],
                      blw + (uint32_t)(nj2 * 16 * ROWB) + ko);
            }
#pragma unroll
            for (int mi = 0; mi < 4; mi++)
#pragma unroll
                for (int nj = 0; nj < 4; nj++) {
                    mma16816(acc[mi][nj], ah[mi], bh[nj]);   // hi*hi
                    mma16816(acc[mi][nj], ah[mi], bl[nj]);   // hi*lo
                    mma16816(acc[mi][nj], al[mi], bh[nj]);   // lo*hi
                }
        }
        __syncthreads();   // done reading bf16 tiles before next convert
    }

    // ---- Epilogue: bias add + scatter store ----
    const float* ebp = eb + (size_t)e * DDIM + n0;
#pragma unroll
    for (int nj = 0; nj < 4; nj++) {
        const int col = wn * 32 + nj * 8 + (lane & 3) * 2;
        const float b0 = __ldg(ebp + col);
        const float b1 = __ldg(ebp + col + 1);
#pragma unroll
        for (int mi = 0; mi < 4; mi++) {
            const int r0 = wm * 64 + mi * 16 + (lane >> 2);
            const int r1 = r0 + 8;
            if (m0 + r0 < cnt) {
                float2 v = { acc[mi][nj][0] + b0, acc[mi][nj][1] + b1 };
                *(float2*)(out + (size_t)srow[r0] * DDIM + n0 + col) = v;
            }
            if (m0 + r1 < cnt) {
                float2 v = { acc[mi][nj][2] + b0, acc[mi][nj][3] + b1 };
                *(float2*)(out + (size_t)srow[r1] * DDIM + n0 + col) = v;
            }
        }
    }
}

// ---------------------------------------------------------------------------
// kernel_launch
// inputs: x[N,D] f32, router_w[E,D] f32, router_b[E] f32,
//         expert_w[E,D,D] f32, expert_b[E,D] f32 ; output f32 [N,D]
// ---------------------------------------------------------------------------
extern "C" void kernel_launch(void* const* d_in, const int* in_sizes, int n_in,
                              void* d_out, int out_size) {
    const float* x   = (const float*)d_in[0];
    const float* rw  = (const float*)d_in[1];
    const float* rb  = (const float*)d_in[2];
    const float* ew  = (const float*)d_in[3];
    const float* ebv = (const float*)d_in[4];
    float* out = (float*)d_out;

    cudaFuncSetAttribute(moe_gemm_mma,
                         cudaFuncAttributeMaxDynamicSharedMemorySize,
                         SMEM_TOTAL);

    zero_cnt_kernel<<<1, 32>>>();
    router_kernel<<<N_TOK / 8, 256>>>(x, rw, rb);

    dim3 grid(DDIM / BN, N_TOK / BM, NEXP);
    moe_gemm_mma<<<grid, GT, SMEM_TOTAL>>>(x, ew, ebv, out);
}

// round 12
// speedup vs baseline: 2.4914x; 1.2581x over previous
#include <cuda_runtime.h>
#include <cuda_bf16.h>
#include <cstdint>

#define N_TOK 16384
#define DDIM  1024
#define NEXP  8

#define BM 128
#define BN 128
#define BK 64
#define NCHUNK (DDIM / BK)       // 16
#define GT 256                   // 8 warps

// ---- shared memory layout ----
// bf16 tiles only (double buffered): rows padded to 72 bf16 (144 B).
#define ROWB   144
#define MATB   (BM * ROWB)                // 18432 B per matrix tile
#define STAGEB (4 * MATB)                 // A_hi, A_lo, B_hi, B_lo = 73728 B
#define OFF_AHI 0
#define OFF_ALO (1 * MATB)
#define OFF_BHI (2 * MATB)
#define OFF_BLO (3 * MATB)
#define SM_SROW 0
#define SM_BF   512
#define SMEM_TOTAL (SM_BF + 2 * STAGEB)   // 147968 B

// ---------------------------------------------------------------------------
// Device scratch: ONLY the small routing tables.
// ---------------------------------------------------------------------------
__device__ int g_cnt[NEXP];
__device__ int g_idx[NEXP * N_TOK];

// ---------------------------------------------------------------------------
// PTX helpers (sm_80-level only)
// ---------------------------------------------------------------------------
__device__ __forceinline__ uint32_t smem_u32(const void* p) {
    uint32_t a;
    asm("{ .reg .u64 t; cvta.to.shared.u64 t, %1; cvt.u32.u64 %0, t; }"
        : "=r"(a) : "l"(p));
    return a;
}
__device__ __forceinline__ void ldsm4(uint32_t& r0, uint32_t& r1,
                                      uint32_t& r2, uint32_t& r3, uint32_t a) {
    asm volatile("ldmatrix.sync.aligned.m8n8.x4.shared.b16 {%0,%1,%2,%3}, [%4];"
                 : "=r"(r0), "=r"(r1), "=r"(r2), "=r"(r3) : "r"(a));
}
__device__ __forceinline__ void mma16816(float* d, const uint32_t* a,
                                         const uint32_t* b) {
    asm volatile("mma.sync.aligned.m16n8k16.row.col.f32.bf16.bf16.f32 "
                 "{%0,%1,%2,%3}, {%4,%5,%6,%7}, {%8,%9}, {%0,%1,%2,%3};"
                 : "+f"(d[0]), "+f"(d[1]), "+f"(d[2]), "+f"(d[3])
                 : "r"(a[0]), "r"(a[1]), "r"(a[2]), "r"(a[3]),
                   "r"(b[0]), "r"(b[1]));
}
// Split a float pair into packed-bf16 hi and lo residual (lo = f - bf16(f)).
__device__ __forceinline__ void pack_split(float f0, float f1,
                                           uint32_t& hi, uint32_t& lo) {
    asm("cvt.rn.bf16x2.f32 %0, %1, %2;" : "=r"(hi) : "f"(f1), "f"(f0));
    float h0 = __uint_as_float(hi << 16);
    float h1 = __uint_as_float(hi & 0xffff0000u);
    float r0 = f0 - h0;
    float r1 = f1 - h1;
    asm("cvt.rn.bf16x2.f32 %0, %1, %2;" : "=r"(lo) : "f"(r1), "f"(r0));
}
__device__ __forceinline__ void sts2(uint32_t a, uint32_t v0, uint32_t v1) {
    asm volatile("st.shared.v2.u32 [%0], {%1,%2};" :: "r"(a), "r"(v0), "r"(v1));
}

// ---------------------------------------------------------------------------
// Kernel 0: zero per-expert counters (graph replays need this every launch).
// ---------------------------------------------------------------------------
__global__ void zero_cnt_kernel() {
    if (threadIdx.x < NEXP) g_cnt[threadIdx.x] = 0;
}

// ---------------------------------------------------------------------------
// Kernel 1: router. One warp/token; argmax, first-index tie-break.
// ---------------------------------------------------------------------------
__global__ void router_kernel(const float* __restrict__ x,
                              const float* __restrict__ rw,
                              const float* __restrict__ rb) {
    int gwarp = (int)((blockIdx.x * blockDim.x + threadIdx.x) >> 5);
    int lane  = threadIdx.x & 31;
    if (gwarp >= N_TOK) return;
    const float* xr = x + (size_t)gwarp * DDIM;
    float acc[NEXP];
#pragma unroll
    for (int e = 0; e < NEXP; e++) acc[e] = 0.f;
    for (int k = lane; k < DDIM; k += 32) {
        float xv = __ldg(xr + k);
#pragma unroll
        for (int e = 0; e < NEXP; e++)
            acc[e] = fmaf(xv, __ldg(rw + e * DDIM + k), acc[e]);
    }
#pragma unroll
    for (int e = 0; e < NEXP; e++)
#pragma unroll
        for (int off = 16; off; off >>= 1)
            acc[e] += __shfl_xor_sync(0xffffffffu, acc[e], off);
    if (lane == 0) {
        int best = 0;
        float bv = acc[0] + rb[0];
#pragma unroll
        for (int e = 1; e < NEXP; e++) {
            float v = acc[e] + rb[e];
            if (v > bv) { bv = v; best = e; }
        }
        int pos = atomicAdd(&g_cnt[best], 1);
        g_idx[best * N_TOK + pos] = gwarp;
    }
}

// ---------------------------------------------------------------------------
// Kernel 2: grouped gather-GEMM, mma.sync bf16 hi/lo split.
//   out[tok, n] = sum_k x[tok,k] * ew[e,n,k] + eb[e,n]
// Register-staged f32 loads -> in-register split -> bf16 hi/lo smem tiles
// (double buffered, ONE __syncthreads per chunk). Per chunk: 4 k-steps x
// (12 ldmatrix.x4 + 48 HMMA: hihi + hilo + lohi). B fragments are loaded
// inside the nj2 loop to cap register pressure (no spills).
// ---------------------------------------------------------------------------
__global__ __launch_bounds__(GT, 1)
void moe_gemm_mma(const float* __restrict__ x,
                  const float* __restrict__ ew,
                  const float* __restrict__ eb,
                  float* __restrict__ out) {
    const int e   = blockIdx.z;
    const int cnt = g_cnt[e];
    const int m0  = blockIdx.y * BM;
    if (m0 >= cnt) return;
    const int n0  = blockIdx.x * BN;

    extern __shared__ __align__(256) char smem[];
    int* srow = (int*)(smem + SM_SROW);
    const uint32_t sb = smem_u32(smem);
    const int tid  = threadIdx.x;
    const int lane = tid & 31;
    const int warp = tid >> 5;
    const int wm   = warp & 1;    // 64-row half (M)
    const int wn   = warp >> 1;   // 32-col quarter (N)

    if (tid < BM) {
        int r = m0 + tid;
        srow[tid] = g_idx[e * N_TOK + (r < cnt ? r : m0)];
    }
    __syncthreads();

    // ---- per-thread load plan: 8 float4 of A + 8 of B per chunk ----
    const float* wB = ew + ((size_t)e * DDIM + n0) * DDIM;
    uint32_t axoff[8], bxoff[8];    // element offsets (fit in 32 bits)
    const int prow  = tid >> 4;     // base row 0..15
    const int piece = tid & 15;     // float4 index within 64-col row
#pragma unroll
    for (int rep = 0; rep < 8; rep++) {
        int row = prow + rep * 16;                   // 0..127
        axoff[rep] = (uint32_t)(srow[row] * DDIM + piece * 4);
        bxoff[rep] = (uint32_t)(row * DDIM + piece * 4);
    }

    float4 ra[8], rb4[8];
    auto gload = [&](int t) {
        const uint32_t kg = (uint32_t)(t * BK);
#pragma unroll
        for (int rep = 0; rep < 8; rep++) {
            ra[rep]  = *(const float4*)(x  + axoff[rep] + kg);
            rb4[rep] = *(const float4*)(wB + bxoff[rep] + kg);
        }
    };
    auto convert_store = [&](int s) {
        const uint32_t bst = sb + SM_BF + (uint32_t)s * STAGEB;
#pragma unroll
        for (int rep = 0; rep < 8; rep++) {
            int row = prow + rep * 16;
            uint32_t bdst = bst + (uint32_t)(row * ROWB + piece * 8);
            uint32_t h0, l0, h1, l1;
            pack_split(ra[rep].x, ra[rep].y, h0, l0);
            pack_split(ra[rep].z, ra[rep].w, h1, l1);
            sts2(bdst + OFF_AHI, h0, h1);
            sts2(bdst + OFF_ALO, l0, l1);
            pack_split(rb4[rep].x, rb4[rep].y, h0, l0);
            pack_split(rb4[rep].z, rb4[rep].w, h1, l1);
            sts2(bdst + OFF_BHI, h0, h1);
            sts2(bdst + OFF_BLO, l0, l1);
        }
    };

    // ---- ldmatrix per-thread base offsets (within a bf16 tile) ----
    const uint32_t a_base =
        (uint32_t)((wm * 64 + (lane & 15)) * ROWB + ((lane >> 4) << 3) * 2);
    const uint32_t b_base =
        (uint32_t)((wn * 32 + (lane & 7) + ((lane >> 4) << 3)) * ROWB +
                   (((lane >> 3) & 1) << 3) * 2);

    float acc[4][4][4];
#pragma unroll
    for (int mi = 0; mi < 4; mi++)
#pragma unroll
        for (int nj = 0; nj < 4; nj++)
#pragma unroll
            for (int q = 0; q < 4; q++) acc[mi][nj][q] = 0.f;

    // Prologue: chunk 0 converted into buf 0; chunk 1 staged in regs.
    gload(0);
    convert_store(0);
    gload(1);
    __syncthreads();                  // buf0 ready for all warps

    for (int t = 0; t < NCHUNK; t++) {
        const int buf = t & 1;
        // Convert chunk t+1 into buf^1 (its previous reader, MMA t-1,
        // finished before the barrier that ended iteration t-1).
        if (t + 1 < NCHUNK) convert_store(buf ^ 1);
        if (t + 2 < NCHUNK) gload(t + 2);

        const uint32_t bst = sb + SM_BF + (uint32_t)buf * STAGEB;
        const uint32_t ahw = bst + OFF_AHI + a_base;
        const uint32_t alw = bst + OFF_ALO + a_base;
        const uint32_t bhw = bst + OFF_BHI + b_base;
        const uint32_t blw = bst + OFF_BLO + b_base;
#pragma unroll
        for (int ks = 0; ks < BK / 16; ks++) {           // 4 k-steps
            const uint32_t ko = (uint32_t)(ks * 16 * 2); // 32 B per step
            uint32_t ah[4][4], al[4][4];
#pragma unroll
            for (int mi = 0; mi < 4; mi++) {
                ldsm4(ah[mi][0], ah[mi][1], ah[mi][2], ah[mi][3],
                      ahw + (uint32_t)(mi * 16 * ROWB) + ko);
                ldsm4(al[mi][0], al[mi][1], al[mi][2], al[mi][3],
                      alw + (uint32_t)(mi * 16 * ROWB) + ko);
            }
#pragma unroll
            for (int nj2 = 0; nj2 < 2; nj2++) {
                // B fragments loaded here and consumed immediately
                // (caps peak register pressure).
                uint32_t bh0[2], bh1[2], bl0[2], bl1[2];
                ldsm4(bh0[0], bh0[1], bh1[0], bh1[1],
                      bhw + (uint32_t)(nj2 * 16 * ROWB) + ko);
                ldsm4(bl0[0], bl0[1], bl1[0], bl1[1],
                      blw + (uint32_t)(nj2 * 16 * ROWB) + ko);
#pragma unroll
                for (int mi = 0; mi < 4; mi++) {
                    float* a0 = acc[mi][nj2 * 2];
                    float* a1 = acc[mi][nj2 * 2 + 1];
                    mma16816(a0, ah[mi], bh0);   // hi*hi
                    mma16816(a0, ah[mi], bl0);   // hi*lo
                    mma16816(a0, al[mi], bh0);   // lo*hi
                    mma16816(a1, ah[mi], bh1);
                    mma16816(a1, ah[mi], bl1);
                    mma16816(a1, al[mi], bh1);
                }
            }
        }
        __syncthreads();   // buf^1 fully written + buf fully read
    }

    // ---- Epilogue: bias add + scatter store ----
    const float* ebp = eb + (size_t)e * DDIM + n0;
#pragma unroll
    for (int nj = 0; nj < 4; nj++) {
        const int col = wn * 32 + nj * 8 + (lane & 3) * 2;
        const float b0 = __ldg(ebp + col);
        const float b1 = __ldg(ebp + col + 1);
#pragma unroll
        for (int mi = 0; mi < 4; mi++) {
            const int r0 = wm * 64 + mi * 16 + (lane >> 2);
            const int r1 = r0 + 8;
            if (m0 + r0 < cnt) {
                float2 v = { acc[mi][nj][0] + b0, acc[mi][nj][1] + b1 };
                *(float2*)(out + (size_t)srow[r0] * DDIM + n0 + col) = v;
            }
            if (m0 + r1 < cnt) {
                float2 v = { acc[mi][nj][2] + b0, acc[mi][nj][3] + b1 };
                *(float2*)(out + (size_t)srow[r1] * DDIM + n0 + col) = v;
            }
        }
    }
}

// ---------------------------------------------------------------------------
// kernel_launch
// inputs: x[N,D] f32, router_w[E,D] f32, router_b[E] f32,
//         expert_w[E,D,D] f32, expert_b[E,D] f32 ; output f32 [N,D]
// ---------------------------------------------------------------------------
extern "C" void kernel_launch(void* const* d_in, const int* in_sizes, int n_in,
                              void* d_out, int out_size) {
    const float* x   = (const float*)d_in[0];
    const float* rw  = (const float*)d_in[1];
    const float* rb  = (const float*)d_in[2];
    const float* ew  = (const float*)d_in[3];
    const float* ebv = (const float*)d_in[4];
    float* out = (float*)d_out;

    cudaFuncSetAttribute(moe_gemm_mma,
                         cudaFuncAttributeMaxDynamicSharedMemorySize,
                         SMEM_TOTAL);

    zero_cnt_kernel<<<1, 32>>>();
    router_kernel<<<N_TOK / 8, 256>>>(x, rw, rb);

    dim3 grid(DDIM / BN, N_TOK / BM, NEXP);
    moe_gemm_mma<<<grid, GT, SMEM_TOTAL>>>(x, ew, ebv, out);
}